// round 1
// baseline (speedup 1.0000x reference)
#include <cuda_runtime.h>

#define BB 2
#define SS 2048
#define DD 512
#define HH 8
#define DHH 64
#define LR 7

// scratch for Q and K projections (8 MB each)
__device__ float g_q[BB * SS * DD];
__device__ float g_k[BB * SS * DD];

// ---------------------------------------------------------------------------
// Kernel 1: Q = HS @ Wq, K = HS @ Wk  (classic 128x128x8 SGEMM, 8x8 reg tile)
// grid = (N/128, M/128, 2)   z=0 -> Wq->g_q, z=1 -> Wk->g_k
// ---------------------------------------------------------------------------
__global__ __launch_bounds__(256, 2)
void proj_gemm(const float* __restrict__ A,
               const float* __restrict__ Wq,
               const float* __restrict__ Wk) {
    const int M = BB * SS;
    const int N = DD;
    const int K = DD;

    const float* W = (blockIdx.z == 0) ? Wq : Wk;
    float* Cbase = (blockIdx.z == 0) ? g_q : g_k;

    __shared__ float As[8][128];
    __shared__ float Bs[8][128];

    const int tid = threadIdx.x;
    const int tx = tid & 15;   // 0..15 (column group)
    const int ty = tid >> 4;   // 0..15 (row group)

    const int rowA = blockIdx.y * 128;
    const int colB = blockIdx.x * 128;

    // A tile load: 128 rows x 8 cols = 256 float4, 1 per thread
    const int a_r = tid >> 1;          // 0..127
    const int a_c = (tid & 1) * 4;     // 0 or 4
    // W tile load: 8 rows x 128 cols = 256 float4, 1 per thread
    const int b_r = tid >> 5;          // 0..7
    const int b_c = (tid & 31) * 4;    // 0..124

    const float* Aptr = A + (size_t)(rowA + a_r) * K + a_c;
    const float* Wptr = W + (size_t)b_r * N + colB + b_c;

    float acc[8][8];
#pragma unroll
    for (int i = 0; i < 8; i++)
#pragma unroll
        for (int j = 0; j < 8; j++) acc[i][j] = 0.f;

    for (int kt = 0; kt < K; kt += 8) {
        float4 av = *(const float4*)(Aptr + kt);
        float4 bv = *(const float4*)(Wptr + (size_t)kt * N);
        __syncthreads();
        As[a_c + 0][a_r] = av.x;
        As[a_c + 1][a_r] = av.y;
        As[a_c + 2][a_r] = av.z;
        As[a_c + 3][a_r] = av.w;
        *(float4*)&Bs[b_r][b_c] = bv;
        __syncthreads();

#pragma unroll
        for (int kk = 0; kk < 8; kk++) {
            float ra[8], rb[8];
            float4 ra0 = *(const float4*)&As[kk][ty * 8];
            float4 ra1 = *(const float4*)&As[kk][ty * 8 + 4];
            float4 rb0 = *(const float4*)&Bs[kk][tx * 8];
            float4 rb1 = *(const float4*)&Bs[kk][tx * 8 + 4];
            ra[0] = ra0.x; ra[1] = ra0.y; ra[2] = ra0.z; ra[3] = ra0.w;
            ra[4] = ra1.x; ra[5] = ra1.y; ra[6] = ra1.z; ra[7] = ra1.w;
            rb[0] = rb0.x; rb[1] = rb0.y; rb[2] = rb0.z; rb[3] = rb0.w;
            rb[4] = rb1.x; rb[5] = rb1.y; rb[6] = rb1.z; rb[7] = rb1.w;
#pragma unroll
            for (int i = 0; i < 8; i++)
#pragma unroll
                for (int j = 0; j < 8; j++)
                    acc[i][j] += ra[i] * rb[j];
        }
    }

    float* Cp = Cbase + (size_t)(rowA + ty * 8) * N + colB + tx * 8;
#pragma unroll
    for (int i = 0; i < 8; i++) {
        *(float4*)(Cp + (size_t)i * N) =
            make_float4(acc[i][0], acc[i][1], acc[i][2], acc[i][3]);
        *(float4*)(Cp + (size_t)i * N + 4) =
            make_float4(acc[i][4], acc[i][5], acc[i][6], acc[i][7]);
    }
}

// ---------------------------------------------------------------------------
// Kernel 2: band-softmax attention + context
// grid = (S, B), 256 threads (8 warps = 8 heads)
// For row i: scores over j in [i-7, i+7] (15 entries, clamped/masked at edges),
// band softmax (full-softmax normalizer cancels; +1e-6 term dropped, ~1.4e-4
// relative perturbation), then context[b,h,i,:] = sum_j w[h][j] * hs[b,j,:].
// ---------------------------------------------------------------------------
__global__ __launch_bounds__(256)
void band_attn(const float* __restrict__ hs, float* __restrict__ out) {
    const int b = blockIdx.y;
    const int i = blockIdx.x;

    __shared__ float sh_hs[15 * DD];   // 30 KB: the 15 band hidden rows
    __shared__ float sh_w[HH][16];     // per-head band weights

    const int tid = threadIdx.x;

    // stage the (clamped) 15 hidden rows into smem
    for (int idx = tid; idx < 15 * DD; idx += 256) {
        int jj = idx >> 9;          // /512
        int d = idx & (DD - 1);
        int j = i - LR + jj;
        j = j < 0 ? 0 : (j >= SS ? SS - 1 : j);
        sh_hs[idx] = hs[((size_t)b * SS + j) * DD + d];
    }

    const int w = tid >> 5;      // warp id = head
    const int lane = tid & 31;

    const float* qrow = g_q + ((size_t)b * SS + i) * DD + w * DHH;
    float q0 = qrow[lane];
    float q1 = qrow[lane + 32];

    float sc[15];
#pragma unroll
    for (int jj = 0; jj < 15; jj++) {
        int j = i - LR + jj;
        bool valid = (j >= 0) && (j < SS);
        int jc = j < 0 ? 0 : (j >= SS ? SS - 1 : j);
        const float* krow = g_k + ((size_t)b * SS + jc) * DD + w * DHH;
        float p = q0 * krow[lane] + q1 * krow[lane + 32];
#pragma unroll
        for (int o = 16; o > 0; o >>= 1)
            p += __shfl_xor_sync(0xffffffffu, p, o);
        sc[jj] = valid ? p * 0.125f : -1e30f;
    }

    float m = -1e30f;
#pragma unroll
    for (int jj = 0; jj < 15; jj++) m = fmaxf(m, sc[jj]);
    float ssum = 0.f;
#pragma unroll
    for (int jj = 0; jj < 15; jj++) {
        sc[jj] = __expf(sc[jj] - m);
        ssum += sc[jj];
    }
    float inv = 1.f / ssum;
    if (lane == 0) {
#pragma unroll
        for (int jj = 0; jj < 15; jj++) sh_w[w][jj] = sc[jj] * inv;
    }
    __syncthreads();

    // context: out[b,h,i,:] = sum_jj w[h][jj] * sh_hs[jj][:]
#pragma unroll
    for (int h = 0; h < HH; h++) {
        float wreg[15];
#pragma unroll
        for (int jj = 0; jj < 15; jj++) wreg[jj] = sh_w[h][jj];
        for (int d = tid; d < DD; d += 256) {
            float acc = 0.f;
#pragma unroll
            for (int jj = 0; jj < 15; jj++)
                acc += wreg[jj] * sh_hs[jj * DD + d];
            out[(((size_t)b * HH + h) * SS + i) * DD + d] = acc;
        }
    }
}

// ---------------------------------------------------------------------------
extern "C" void kernel_launch(void* const* d_in, const int* in_sizes, int n_in,
                              void* d_out, int out_size) {
    const float* hs = (const float*)d_in[0];
    const float* Wq = (const float*)d_in[1];
    const float* Wk = (const float*)d_in[2];
    float* out = (float*)d_out;

    dim3 g1(DD / 128, (BB * SS) / 128, 2);   // (4, 32, 2)
    proj_gemm<<<g1, 256>>>(hs, Wq, Wk);

    dim3 g2(SS, BB);                          // (2048, 2)
    band_attn<<<g2, 256>>>(hs, out);
}

// round 4
// speedup vs baseline: 1.8987x; 1.8987x over previous
#include <cuda_runtime.h>
#include <cuda_bf16.h>
#include <cstdint>

#define BB 2
#define SS 2048
#define DD 512
#define HH 8
#define LR 7
#define MTOT (BB*SS)        // 4096
#define K3 (3*DD)           // 1536

// scratch
__device__ float g_q[MTOT * DD];
__device__ float g_k[MTOT * DD];
__device__ __nv_bfloat16 g_a3[MTOT * K3];   // [hi | lo | hi] along K
__device__ __nv_bfloat16 g_b3q[DD * K3];    // [hi | hi | lo] along K, rows = n
__device__ __nv_bfloat16 g_b3k[DD * K3];

#define SWZ128(off) ((off) ^ (((off) >> 3) & 0x70))

__device__ __forceinline__ uint32_t smem_u32(const void* p) {
    uint32_t a;
    asm("{ .reg .u64 t; cvta.to.shared.u64 t, %1; cvt.u32.u64 %0, t; }" : "=r"(a) : "l"(p));
    return a;
}
__device__ __forceinline__ void cp16(uint32_t s, const void* g) {
    asm volatile("cp.async.cg.shared.global [%0], [%1], 16;" :: "r"(s), "l"(g));
}
#define CP_COMMIT() asm volatile("cp.async.commit_group;" ::: "memory")

__device__ __forceinline__ void ldm_x4(uint32_t& r0, uint32_t& r1, uint32_t& r2, uint32_t& r3, uint32_t a) {
    asm volatile("ldmatrix.sync.aligned.m8n8.x4.shared.b16 {%0,%1,%2,%3}, [%4];"
                 : "=r"(r0), "=r"(r1), "=r"(r2), "=r"(r3) : "r"(a));
}
__device__ __forceinline__ void ldm_x2(uint32_t& r0, uint32_t& r1, uint32_t a) {
    asm volatile("ldmatrix.sync.aligned.m8n8.x2.shared.b16 {%0,%1}, [%2];"
                 : "=r"(r0), "=r"(r1) : "r"(a));
}
__device__ __forceinline__ void mma16816(float* d, const uint32_t* a, const uint32_t* b) {
    asm volatile("mma.sync.aligned.m16n8k16.row.col.f32.bf16.bf16.f32 "
                 "{%0,%1,%2,%3}, {%4,%5,%6,%7}, {%8,%9}, {%0,%1,%2,%3};"
                 : "+f"(d[0]), "+f"(d[1]), "+f"(d[2]), "+f"(d[3])
                 : "r"(a[0]), "r"(a[1]), "r"(a[2]), "r"(a[3]), "r"(b[0]), "r"(b[1]));
}

// ---------------------------------------------------------------------------
// split hidden_states into bf16 hi/lo, tripled K layout [hi|lo|hi]
// ---------------------------------------------------------------------------
__global__ void split_hs(const float* __restrict__ hs) {
    int idx = blockIdx.x * 256 + threadIdx.x;     // float4 index
    int m = idx >> 7;
    int c = idx & 127;
    float4 v = ((const float4*)hs)[idx];
    __nv_bfloat16 hx = __float2bfloat16(v.x), hy = __float2bfloat16(v.y);
    __nv_bfloat16 hz = __float2bfloat16(v.z), hw = __float2bfloat16(v.w);
    __nv_bfloat16 lx = __float2bfloat16(v.x - __bfloat162float(hx));
    __nv_bfloat16 ly = __float2bfloat16(v.y - __bfloat162float(hy));
    __nv_bfloat16 lz = __float2bfloat16(v.z - __bfloat162float(hz));
    __nv_bfloat16 lw = __float2bfloat16(v.w - __bfloat162float(hw));
    __nv_bfloat162 H0; H0.x = hx; H0.y = hy;
    __nv_bfloat162 H1; H1.x = hz; H1.y = hw;
    __nv_bfloat162 L0; L0.x = lx; L0.y = ly;
    __nv_bfloat162 L1; L1.x = lz; L1.y = lw;
    __nv_bfloat16* p = g_a3 + (size_t)m * K3 + 4 * c;
    *(__nv_bfloat162*)(p)          = H0; *(__nv_bfloat162*)(p + 2)          = H1;
    *(__nv_bfloat162*)(p + DD)     = L0; *(__nv_bfloat162*)(p + DD + 2)     = L1;
    *(__nv_bfloat162*)(p + 2*DD)   = H0; *(__nv_bfloat162*)(p + 2*DD + 2)   = H1;
}

// ---------------------------------------------------------------------------
// split + transpose W (stored [k, n]) into B3 [n, 3K] = [hi|hi|lo]
// ---------------------------------------------------------------------------
__global__ void split_w(const float* __restrict__ Wq, const float* __restrict__ Wk) {
    __shared__ float t[32][33];
    const float* W = blockIdx.z ? Wk : Wq;
    __nv_bfloat16* B3 = blockIdx.z ? g_b3k : g_b3q;
    int n0 = blockIdx.x * 32, k0 = blockIdx.y * 32;
    int tx = threadIdx.x, ty = threadIdx.y;           // (32, 8)
#pragma unroll
    for (int r = 0; r < 4; r++)
        t[ty + r * 8][tx] = W[(size_t)(k0 + ty + r * 8) * DD + n0 + tx];
    __syncthreads();
#pragma unroll
    for (int r = 0; r < 4; r++) {
        int n = n0 + ty + r * 8, k = k0 + tx;
        float v = t[tx][ty + r * 8];
        __nv_bfloat16 h = __float2bfloat16(v);
        __nv_bfloat16 l = __float2bfloat16(v - __bfloat162float(h));
        B3[(size_t)n * K3 + k]        = h;
        B3[(size_t)n * K3 + DD + k]   = h;
        B3[(size_t)n * K3 + 2*DD + k] = l;
    }
}

// ---------------------------------------------------------------------------
// mma.sync bf16 GEMM: C[4096,512] = A3[4096,1536] * B3[512,1536]^T, f32 acc
// CTA tile 128x128, 8 warps of 64x32, K-tile 64, 3-stage cp.async pipeline
// ---------------------------------------------------------------------------
#define MT 128
#define NT 128
#define KT 64
#define NK 24          // 1536/64
#define STG 32768u     // 16KB A + 16KB B
#define NSTG 3
#define GEMM_SMEM (NSTG * STG)

__device__ __forceinline__ void load_tile(int tile, int stg,
                                          const char* Ab, const char* Bb,
                                          uint32_t sb, int tid) {
    size_t koff = (size_t)tile * (KT * 2);
    uint32_t sA = sb + (uint32_t)stg * STG;
    uint32_t sB = sA + 16384u;
#pragma unroll
    for (int c = 0; c < 4; c++) {
        int q = tid + c * 256;
        int r = q >> 3, col = (q & 7) * 16;
        cp16(sA + SWZ128(r * 128 + col), Ab + (size_t)r * (K3 * 2) + koff + col);
    }
#pragma unroll
    for (int c = 0; c < 4; c++) {
        int q = tid + c * 256;
        int r = q >> 3, col = (q & 7) * 16;
        cp16(sB + SWZ128(r * 128 + col), Bb + (size_t)r * (K3 * 2) + koff + col);
    }
}

__global__ __launch_bounds__(256, 2)
void gemm3() {
    extern __shared__ char smem[];
    uint32_t sb = smem_u32(smem);
    const int tid = threadIdx.x, wid = tid >> 5, lane = tid & 31;
    const int m0 = blockIdx.x * MT;
    const int n0 = blockIdx.y * NT;
    const __nv_bfloat16* B3 = blockIdx.z ? g_b3k : g_b3q;
    float* C = blockIdx.z ? g_k : g_q;

    const char* Ab = (const char*)g_a3 + (size_t)m0 * (K3 * 2);
    const char* Bb = (const char*)B3 + (size_t)n0 * (K3 * 2);

    const int wm = wid & 1;     // 2 warps along M (64 rows each)
    const int wn = wid >> 1;    // 4 warps along N (32 cols each)

    float acc[4][4][4];
#pragma unroll
    for (int i = 0; i < 4; i++)
#pragma unroll
        for (int j = 0; j < 4; j++)
#pragma unroll
            for (int r = 0; r < 4; r++) acc[i][j][r] = 0.f;

    // prologue: tiles 0,1 into stages 0,1
    load_tile(0, 0, Ab, Bb, sb, tid); CP_COMMIT();
    load_tile(1, 1, Ab, Bb, sb, tid); CP_COMMIT();

    // ldmatrix lane address components
    const int a_row = wm * 64 + (lane & 15);         // + mi*16
    const int a_cg  = (lane >> 4) * 16;
    const int b_row = wn * 32 + (lane & 7);          // + ni*8
    const int b_cg  = ((lane >> 3) & 1) * 16;

    for (int t = 0; t < NK; t++) {
        // wait for tile t (pending groups: t, t+1 -> wait until <=1)
        asm volatile("cp.async.wait_group 1;" ::: "memory");
        __syncthreads();   // all warps done reading stage (t+2)%3 (held tile t-1)

        // prefetch tile t+2 into stage (t+2)%3 (!= t%3)
        if (t + 2 < NK)
            load_tile(t + 2, (t + 2) % NSTG, Ab, Bb, sb, tid);
        CP_COMMIT();       // unconditional: keeps group accounting uniform

        uint32_t sA = sb + (uint32_t)(t % NSTG) * STG;
        uint32_t sB = sA + 16384u;
#pragma unroll
        for (int ks = 0; ks < 4; ks++) {
            uint32_t af[4][4], bf[4][2];
#pragma unroll
            for (int mi = 0; mi < 4; mi++)
                ldm_x4(af[mi][0], af[mi][1], af[mi][2], af[mi][3],
                       sA + SWZ128((a_row + mi * 16) * 128 + ks * 32 + a_cg));
#pragma unroll
            for (int ni = 0; ni < 4; ni++)
                ldm_x2(bf[ni][0], bf[ni][1],
                       sB + SWZ128((b_row + ni * 8) * 128 + ks * 32 + b_cg));
#pragma unroll
            for (int mi = 0; mi < 4; mi++)
#pragma unroll
                for (int ni = 0; ni < 4; ni++)
                    mma16816(acc[mi][ni], af[mi], bf[ni]);
        }
    }

    // epilogue: direct float2 stores
    const int er = lane >> 2;          // 0..7
    const int ec = (lane & 3) * 2;     // 0,2,4,6
#pragma unroll
    for (int mi = 0; mi < 4; mi++) {
        int r0 = m0 + wm * 64 + mi * 16 + er;
#pragma unroll
        for (int ni = 0; ni < 4; ni++) {
            int cc = n0 + wn * 32 + ni * 8 + ec;
            *(float2*)(C + (size_t)r0 * DD + cc) = make_float2(acc[mi][ni][0], acc[mi][ni][1]);
            *(float2*)(C + (size_t)(r0 + 8) * DD + cc) = make_float2(acc[mi][ni][2], acc[mi][ni][3]);
        }
    }
}

// ---------------------------------------------------------------------------
// band-softmax attention + context
// ---------------------------------------------------------------------------
__global__ __launch_bounds__(256)
void band_attn(const float* __restrict__ hs, float* __restrict__ out) {
    const int b = blockIdx.y;
    const int i = blockIdx.x;

    __shared__ float sh_hs[15 * DD];   // 30 KB
    __shared__ float sh_w[HH][16];

    const int tid = threadIdx.x;

    for (int idx = tid; idx < 15 * 128; idx += 256) {
        int jj = idx >> 7, c = idx & 127;
        int j = i - LR + jj;
        j = j < 0 ? 0 : (j >= SS ? SS - 1 : j);
        ((float4*)sh_hs)[jj * 128 + c] =
            ((const float4*)(hs + ((size_t)b * SS + j) * DD))[c];
    }

    const int w = tid >> 5;
    const int lane = tid & 31;

    const float* qrow = g_q + ((size_t)b * SS + i) * DD + w * 64;
    float q0 = qrow[lane];
    float q1 = qrow[lane + 32];

    float sc[15];
#pragma unroll
    for (int jj = 0; jj < 15; jj++) {
        int j = i - LR + jj;
        bool valid = (j >= 0) && (j < SS);
        int jc = j < 0 ? 0 : (j >= SS ? SS - 1 : j);
        const float* krow = g_k + ((size_t)b * SS + jc) * DD + w * 64;
        float p = q0 * krow[lane] + q1 * krow[lane + 32];
#pragma unroll
        for (int o = 16; o > 0; o >>= 1)
            p += __shfl_xor_sync(0xffffffffu, p, o);
        sc[jj] = valid ? p * 0.125f : -1e30f;
    }
    float m = -1e30f;
#pragma unroll
    for (int jj = 0; jj < 15; jj++) m = fmaxf(m, sc[jj]);
    float ssum = 0.f;
#pragma unroll
    for (int jj = 0; jj < 15; jj++) { sc[jj] = __expf(sc[jj] - m); ssum += sc[jj]; }
    float inv = 1.f / ssum;
    if (lane == 0) {
#pragma unroll
        for (int jj = 0; jj < 15; jj++) sh_w[w][jj] = sc[jj] * inv;
    }
    __syncthreads();

    const float2* sh2 = (const float2*)sh_hs;
    const int d2 = tid;
#pragma unroll
    for (int pass = 0; pass < 2; pass++) {
        float wr[4][15];
#pragma unroll
        for (int h = 0; h < 4; h++)
#pragma unroll
            for (int jj = 0; jj < 15; jj++) wr[h][jj] = sh_w[pass * 4 + h][jj];
        float2 acc[4] = {{0.f,0.f},{0.f,0.f},{0.f,0.f},{0.f,0.f}};
#pragma unroll
        for (int jj = 0; jj < 15; jj++) {
            float2 v = sh2[jj * 256 + d2];
#pragma unroll
            for (int h = 0; h < 4; h++) {
                acc[h].x += wr[h][jj] * v.x;
                acc[h].y += wr[h][jj] * v.y;
            }
        }
#pragma unroll
        for (int h = 0; h < 4; h++)
            *(float2*)(out + (((size_t)b * HH + pass * 4 + h) * SS + i) * DD + 2 * d2) = acc[h];
    }
}

// ---------------------------------------------------------------------------
extern "C" void kernel_launch(void* const* d_in, const int* in_sizes, int n_in,
                              void* d_out, int out_size) {
    const float* hs = (const float*)d_in[0];
    const float* Wq = (const float*)d_in[1];
    const float* Wk = (const float*)d_in[2];
    float* out = (float*)d_out;

    cudaFuncSetAttribute(gemm3, cudaFuncAttributeMaxDynamicSharedMemorySize, GEMM_SMEM);

    split_hs<<<2048, 256>>>(hs);
    split_w<<<dim3(16, 16, 2), dim3(32, 8)>>>(Wq, Wk);
    gemm3<<<dim3(32, 4, 2), 256, GEMM_SMEM>>>();
    band_attn<<<dim3(SS, BB), 256>>>(hs, out);
}